// round 1
// baseline (speedup 1.0000x reference)
#include <cuda_runtime.h>
#include <cstdint>

#define N_NODES 100000
#define N_EDGES 3200000
#define ET      (N_EDGES + N_NODES)   // 3,300,000 (edges + self loops)
#define CI      128
#define CO      64

// ---------------- device scratch (static, no allocation) ----------------
__device__ float g_xl[(size_t)N_NODES * CO];   // 25.6 MB
__device__ float g_si[N_NODES];
__device__ float g_sj[N_NODES];
__device__ int   g_amax[N_NODES];
__device__ float g_denom[N_NODES];
__device__ float g_ex[ET];                     // 13.2 MB (alpha -> ex)
__device__ float g_agg[(size_t)N_NODES * CO];  // 25.6 MB
__device__ float g_bnsum[2 * CO];              // [sum, sumsq] per channel

// ordered-int encoding for float atomicMax (monotonic for all finite floats)
__device__ __forceinline__ int f2ord(float f) {
    int i = __float_as_int(f);
    return i >= 0 ? i : (i ^ 0x7fffffff);
}
__device__ __forceinline__ float ord2f(int i) {
    return __int_as_float(i >= 0 ? i : (i ^ 0x7fffffff));
}

// ---------------- K0: init ----------------
__global__ __launch_bounds__(256) void k_init() {
    int i = blockIdx.x * 256 + threadIdx.x;
    if (i < N_NODES * CO) g_agg[i] = 0.f;
    if (i < N_NODES) { g_denom[i] = 0.f; g_amax[i] = (int)0x80000000; }
    if (i < 2 * CO) g_bnsum[i] = 0.f;
}

// ---------------- K1: GEMM xl = x @ W^T + b, fused s_i/s_j scores ------
// block = 256 threads, 128 nodes/block; thread = (node, 32-col half)
__global__ __launch_bounds__(256) void k_gemm(
    const float* __restrict__ x,  const float* __restrict__ w,
    const float* __restrict__ lb, const float* __restrict__ emb,
    const float* __restrict__ ai, const float* __restrict__ aj,
    const float* __restrict__ aei, const float* __restrict__ aej)
{
    __shared__ float wsT[128 * 68];   // [k][c], padded row=68 (16B aligned, no bank conflicts)
    int tid = threadIdx.x;
    for (int i = tid; i < CO * CI; i += 256) {
        int c = i >> 7, k = i & 127;  // w is [CO][CI] row-major
        wsT[k * 68 + c] = w[i];
    }
    __syncthreads();

    int m = blockIdx.x * 128 + (tid >> 1);
    bool valid = (m < N_NODES);
    int mc = valid ? m : (N_NODES - 1);      // clamp address, keep lanes alive for shfl
    int g = (tid & 1) * 32;                  // column half offset

    const float* xrow = x + (size_t)mc * CI;
    float acc[32];
#pragma unroll
    for (int c = 0; c < 32; c++) acc[c] = 0.f;

#pragma unroll 8
    for (int k0 = 0; k0 < 128; k0 += 4) {
        float4 xv = *(const float4*)(xrow + k0);
#pragma unroll
        for (int q = 0; q < 4; q++) {
            float xs = (&xv.x)[q];
            const float4* wp = (const float4*)&wsT[(k0 + q) * 68 + g];
#pragma unroll
            for (int j = 0; j < 8; j++) {
                float4 wv = wp[j];
                acc[4 * j + 0] = fmaf(xs, wv.x, acc[4 * j + 0]);
                acc[4 * j + 1] = fmaf(xs, wv.y, acc[4 * j + 1]);
                acc[4 * j + 2] = fmaf(xs, wv.z, acc[4 * j + 2]);
                acc[4 * j + 3] = fmaf(xs, wv.w, acc[4 * j + 3]);
            }
        }
    }

    // epilogue: bias, store xl, fused attention scores
    float pi = 0.f, pj = 0.f;
#pragma unroll
    for (int c = 0; c < 32; c++) {
        float o = acc[c] + __ldg(&lb[g + c]);
        acc[c] = o;
        pi = fmaf(o, __ldg(&ai[g + c]), pi);
        pj = fmaf(o, __ldg(&aj[g + c]), pj);
    }
    if (valid) {
        float4* xlp = (float4*)&g_xl[(size_t)m * CO + g];
#pragma unroll
        for (int j = 0; j < 8; j++)
            xlp[j] = make_float4(acc[4 * j], acc[4 * j + 1], acc[4 * j + 2], acc[4 * j + 3]);
    }
    const float* erow = emb + (size_t)mc * CO + g;
#pragma unroll
    for (int c = 0; c < 32; c += 4) {
        float4 ev = *(const float4*)(erow + c);
        pi = fmaf(ev.x, __ldg(&aei[g + c + 0]), pi);
        pi = fmaf(ev.y, __ldg(&aei[g + c + 1]), pi);
        pi = fmaf(ev.z, __ldg(&aei[g + c + 2]), pi);
        pi = fmaf(ev.w, __ldg(&aei[g + c + 3]), pi);
        pj = fmaf(ev.x, __ldg(&aej[g + c + 0]), pj);
        pj = fmaf(ev.y, __ldg(&aej[g + c + 1]), pj);
        pj = fmaf(ev.z, __ldg(&aej[g + c + 2]), pj);
        pj = fmaf(ev.w, __ldg(&aej[g + c + 3]), pj);
    }
    pi += __shfl_xor_sync(0xffffffffu, pi, 1);
    pj += __shfl_xor_sync(0xffffffffu, pj, 1);
    if (valid && (tid & 1) == 0) { g_si[m] = pi; g_sj[m] = pj; }
}

// ---------------- K2: alpha = lrelu(s_i[d]+s_j[s]), segment max --------
__global__ __launch_bounds__(256) void k_alpha(const int* __restrict__ ei) {
    int e = blockIdx.x * 256 + threadIdx.x;
    if (e >= ET) return;
    int s, d;
    if (e < N_EDGES) { s = ei[e]; d = ei[N_EDGES + e]; }
    else             { s = e - N_EDGES; d = s; }
    float a = g_si[d] + g_sj[s];
    a = a > 0.f ? a : 0.2f * a;
    g_ex[e] = a;
    atomicMax(&g_amax[d], f2ord(a));
}

// ---------------- K3: ex = exp(a - amax[d]), segment sum ---------------
__global__ __launch_bounds__(256) void k_expsum(const int* __restrict__ ei) {
    int e = blockIdx.x * 256 + threadIdx.x;
    if (e >= ET) return;
    int d = (e < N_EDGES) ? ei[N_EDGES + e] : (e - N_EDGES);
    float a  = g_ex[e];
    float mx = ord2f(g_amax[d]);
    float ex = __expf(a - mx);
    g_ex[e] = ex;
    atomicAdd(&g_denom[d], ex);
}

// ---------------- K4: normalize, write att, aggregate ------------------
// 16 threads per edge, each lane owns 4 channels (float4); vector red atomics
__global__ __launch_bounds__(256) void k_agg(const int* __restrict__ ei,
                                             float* __restrict__ att) {
    long long gid = (long long)blockIdx.x * 256 + threadIdx.x;
    long long e = gid >> 4;
    int lane = (int)(gid & 15);
    if (e >= ET) return;
    int s, d;
    if (e < N_EDGES) { s = ei[e]; d = ei[N_EDGES + e]; }
    else             { s = (int)e - N_EDGES; d = s; }
    float w = __fdividef(g_ex[e], g_denom[d]);
    if (lane == 0) att[e] = w;
    float4 v = *(const float4*)&g_xl[(size_t)s * CO + lane * 4];
    float* p = &g_agg[(size_t)d * CO + lane * 4];
    asm volatile("red.global.add.v4.f32 [%0], {%1,%2,%3,%4};"
                 :: "l"(p), "f"(v.x * w), "f"(v.y * w), "f"(v.z * w), "f"(v.w * w)
                 : "memory");
}

// ---------------- K5: BN statistics (sum, sumsq per channel) -----------
__global__ __launch_bounds__(256) void k_stats(const float* __restrict__ bias) {
    __shared__ float sh[512];
    int tid = threadIdx.x;
    int c = tid & 63;
    int rg = tid >> 6;                 // 4 row-groups per block
    float b = __ldg(&bias[c]);
    float s1 = 0.f, s2 = 0.f;
#pragma unroll 4
    for (int i = 0; i < 64; i++) {
        int r = blockIdx.x * 256 + rg + i * 4;
        if (r < N_NODES) {
            float v = g_agg[(size_t)r * CO + c] + b;
            s1 += v;
            s2 += v * v;
        }
    }
    sh[tid] = s1;
    sh[256 + tid] = s2;
    __syncthreads();
    if (tid < 64) {
        float t1 = sh[tid] + sh[64 + tid] + sh[128 + tid] + sh[192 + tid];
        float t2 = sh[256 + tid] + sh[320 + tid] + sh[384 + tid] + sh[448 + tid];
        atomicAdd(&g_bnsum[tid], t1);
        atomicAdd(&g_bnsum[64 + tid], t2);
    }
}

// ---------------- K6: BN apply + leaky-relu -> out ---------------------
__global__ __launch_bounds__(256) void k_out(const float* __restrict__ bias,
                                             const float* __restrict__ gamma,
                                             const float* __restrict__ beta,
                                             float* __restrict__ out) {
    int i = blockIdx.x * 256 + threadIdx.x;
    if (i >= N_NODES * CO) return;
    int c = i & 63;
    float inv_n = 1.f / (float)N_NODES;
    float mu  = g_bnsum[c] * inv_n;
    float var = g_bnsum[64 + c] * inv_n - mu * mu;
    float v = g_agg[i] + __ldg(&bias[c]);
    float o = __ldg(&gamma[c]) * (v - mu) * rsqrtf(var + 1e-5f) + __ldg(&beta[c]);
    out[i] = o > 0.f ? o : 0.01f * o;
}

// ---------------- launch ----------------
extern "C" void kernel_launch(void* const* d_in, const int* in_sizes, int n_in,
                              void* d_out, int out_size) {
    const float* x     = (const float*)d_in[0];
    const int*   ei    = (const int*)  d_in[1];   // [2][E]
    const float* emb   = (const float*)d_in[2];
    const float* lw    = (const float*)d_in[3];
    const float* lb    = (const float*)d_in[4];
    const float* ai    = (const float*)d_in[5];
    const float* aj    = (const float*)d_in[6];
    const float* aei   = (const float*)d_in[7];
    const float* aej   = (const float*)d_in[8];
    const float* bias  = (const float*)d_in[9];
    const float* gamma = (const float*)d_in[10];
    const float* beta  = (const float*)d_in[11];

    float* out = (float*)d_out;                       // [N, 64]
    float* att = out + (size_t)N_NODES * CO;          // [ET, 1, 1]

    k_init  <<<(N_NODES * CO + 255) / 256, 256>>>();
    k_gemm  <<<(N_NODES + 127) / 128, 256>>>(x, lw, lb, emb, ai, aj, aei, aej);
    k_alpha <<<(ET + 255) / 256, 256>>>(ei);
    k_expsum<<<(ET + 255) / 256, 256>>>(ei);
    k_agg   <<<(int)(((long long)ET * 16 + 255) / 256), 256>>>(ei, att);
    k_stats <<<(N_NODES + 255) / 256, 256>>>(bias);
    k_out   <<<(N_NODES * CO + 255) / 256, 256>>>(bias, gamma, beta, out);
}

// round 2
// speedup vs baseline: 1.0588x; 1.0588x over previous
#include <cuda_runtime.h>
#include <cuda_fp16.h>
#include <cstdint>

#define N_NODES 100000
#define N_EDGES 3200000
#define ET      (N_EDGES + N_NODES)   // 3,300,000 (edges + self loops)
#define CI      128
#define CO      64

// ---------------- device scratch (static, no allocation) ----------------
__device__ __align__(16) __half g_xlh[(size_t)N_NODES * CO];  // 12.8 MB (fp16 xl)
__device__ float g_si[N_NODES];
__device__ float g_sj[N_NODES];
__device__ float g_denom[N_NODES];
__device__ float g_ex[ET];                     // 13.2 MB (unnormalized exp)
__device__ float g_agg[(size_t)N_NODES * CO];  // 25.6 MB (unnormalized aggregate)
__device__ float g_bnsum[2 * CO];              // [sum, sumsq] per channel

// ---------------- K0: init ----------------
__global__ __launch_bounds__(256) void k_init() {
    int i = blockIdx.x * 256 + threadIdx.x;
    if (i < N_NODES * CO) g_agg[i] = 0.f;
    if (i < N_NODES) g_denom[i] = 0.f;
    if (i < 2 * CO) g_bnsum[i] = 0.f;
}

// ---------------- K1: GEMM xl = x @ W^T + b, fused s_i/s_j scores ------
// block = 256 threads, 128 nodes/block; thread = (node, 32-col half)
__global__ __launch_bounds__(256) void k_gemm(
    const float* __restrict__ x,  const float* __restrict__ w,
    const float* __restrict__ lb, const float* __restrict__ emb,
    const float* __restrict__ ai, const float* __restrict__ aj,
    const float* __restrict__ aei, const float* __restrict__ aej)
{
    __shared__ float wsT[128 * 68];   // [k][c], padded row=68
    int tid = threadIdx.x;
    for (int i = tid; i < CO * CI; i += 256) {
        int c = i >> 7, k = i & 127;  // w is [CO][CI] row-major
        wsT[k * 68 + c] = w[i];
    }
    __syncthreads();

    int m = blockIdx.x * 128 + (tid >> 1);
    bool valid = (m < N_NODES);
    int mc = valid ? m : (N_NODES - 1);
    int g = (tid & 1) * 32;

    const float* xrow = x + (size_t)mc * CI;
    float acc[32];
#pragma unroll
    for (int c = 0; c < 32; c++) acc[c] = 0.f;

#pragma unroll 8
    for (int k0 = 0; k0 < 128; k0 += 4) {
        float4 xv = *(const float4*)(xrow + k0);
#pragma unroll
        for (int q = 0; q < 4; q++) {
            float xs = (&xv.x)[q];
            const float4* wp = (const float4*)&wsT[(k0 + q) * 68 + g];
#pragma unroll
            for (int j = 0; j < 8; j++) {
                float4 wv = wp[j];
                acc[4 * j + 0] = fmaf(xs, wv.x, acc[4 * j + 0]);
                acc[4 * j + 1] = fmaf(xs, wv.y, acc[4 * j + 1]);
                acc[4 * j + 2] = fmaf(xs, wv.z, acc[4 * j + 2]);
                acc[4 * j + 3] = fmaf(xs, wv.w, acc[4 * j + 3]);
            }
        }
    }

    // epilogue: bias, fused attention scores, fp16 xl store
    float pi = 0.f, pj = 0.f;
#pragma unroll
    for (int c = 0; c < 32; c++) {
        float o = acc[c] + __ldg(&lb[g + c]);
        acc[c] = o;
        pi = fmaf(o, __ldg(&ai[g + c]), pi);
        pj = fmaf(o, __ldg(&aj[g + c]), pj);
    }
    if (valid) {
        __half2 hbuf[16];
#pragma unroll
        for (int j = 0; j < 16; j++)
            hbuf[j] = __floats2half2_rn(acc[2 * j], acc[2 * j + 1]);
        uint4* dst = (uint4*)&g_xlh[(size_t)m * CO + g];
        const uint4* src = (const uint4*)hbuf;
#pragma unroll
        for (int j = 0; j < 4; j++) dst[j] = src[j];
    }
    const float* erow = emb + (size_t)mc * CO + g;
#pragma unroll
    for (int c = 0; c < 32; c += 4) {
        float4 ev = *(const float4*)(erow + c);
        pi = fmaf(ev.x, __ldg(&aei[g + c + 0]), pi);
        pi = fmaf(ev.y, __ldg(&aei[g + c + 1]), pi);
        pi = fmaf(ev.z, __ldg(&aei[g + c + 2]), pi);
        pi = fmaf(ev.w, __ldg(&aei[g + c + 3]), pi);
        pj = fmaf(ev.x, __ldg(&aej[g + c + 0]), pj);
        pj = fmaf(ev.y, __ldg(&aej[g + c + 1]), pj);
        pj = fmaf(ev.z, __ldg(&aej[g + c + 2]), pj);
        pj = fmaf(ev.w, __ldg(&aej[g + c + 3]), pj);
    }
    pi += __shfl_xor_sync(0xffffffffu, pi, 1);
    pj += __shfl_xor_sync(0xffffffffu, pj, 1);
    if (valid && (tid & 1) == 0) { g_si[m] = pi; g_sj[m] = pj; }
}

// ---------------- K2: fused score + exp + denom + aggregate ------------
// 8 threads per edge; each lane owns 8 channels (16B fp16 load, 2x red.v4)
// No segment-max: scores bounded (|a| <= ~13), exp safe in fp32.
// Aggregates UNNORMALIZED: agg[d] += ex_e * xl[s]; denom[d] += ex_e.
__global__ __launch_bounds__(256) void k_score_agg(const int* __restrict__ ei) {
    long long gid = (long long)blockIdx.x * 256 + threadIdx.x;
    long long e = gid >> 3;
    int lane = (int)(gid & 7);
    if (e >= ET) return;
    int s, d;
    if (e < N_EDGES) { s = __ldg(&ei[e]); d = __ldg(&ei[N_EDGES + e]); }
    else             { s = (int)e - N_EDGES; d = s; }
    float a = g_si[d] + g_sj[s];
    a = a > 0.f ? a : 0.2f * a;
    float ex = __expf(a);
    if (lane == 0) {
        g_ex[e] = ex;
        atomicAdd(&g_denom[d], ex);
    }
    uint4 raw = *(const uint4*)&g_xlh[(size_t)s * CO + lane * 8];
    float2 f0 = __half22float2(*(__half2*)&raw.x);
    float2 f1 = __half22float2(*(__half2*)&raw.y);
    float2 f2 = __half22float2(*(__half2*)&raw.z);
    float2 f3 = __half22float2(*(__half2*)&raw.w);
    float* p = &g_agg[(size_t)d * CO + lane * 8];
    asm volatile("red.global.add.v4.f32 [%0], {%1,%2,%3,%4};"
                 :: "l"(p), "f"(f0.x * ex), "f"(f0.y * ex),
                    "f"(f1.x * ex), "f"(f1.y * ex) : "memory");
    asm volatile("red.global.add.v4.f32 [%0], {%1,%2,%3,%4};"
                 :: "l"(p + 4), "f"(f2.x * ex), "f"(f2.y * ex),
                    "f"(f3.x * ex), "f"(f3.y * ex) : "memory");
}

// ---------------- K3: attention weights att[e] = ex[e]/denom[d] --------
__global__ __launch_bounds__(256) void k_att(const int* __restrict__ ei,
                                             float* __restrict__ att) {
    int e = blockIdx.x * 256 + threadIdx.x;
    if (e >= ET) return;
    int d = (e < N_EDGES) ? __ldg(&ei[N_EDGES + e]) : (e - N_EDGES);
    att[e] = __fdividef(g_ex[e], g_denom[d]);
}

// ---------------- K4: BN statistics (normalize agg by denom on the fly)
__global__ __launch_bounds__(256) void k_stats(const float* __restrict__ bias) {
    __shared__ float sh[512];
    int tid = threadIdx.x;
    int c = tid & 63;
    int rg = tid >> 6;
    float b = __ldg(&bias[c]);
    float s1 = 0.f, s2 = 0.f;
#pragma unroll 4
    for (int i = 0; i < 64; i++) {
        int r = blockIdx.x * 256 + rg + i * 4;
        if (r < N_NODES) {
            float v = g_agg[(size_t)r * CO + c] * __frcp_rn(g_denom[r]) + b;
            s1 += v;
            s2 += v * v;
        }
    }
    sh[tid] = s1;
    sh[256 + tid] = s2;
    __syncthreads();
    if (tid < 64) {
        float t1 = sh[tid] + sh[64 + tid] + sh[128 + tid] + sh[192 + tid];
        float t2 = sh[256 + tid] + sh[320 + tid] + sh[384 + tid] + sh[448 + tid];
        atomicAdd(&g_bnsum[tid], t1);
        atomicAdd(&g_bnsum[64 + tid], t2);
    }
}

// ---------------- K5: BN apply + leaky-relu -> out ---------------------
__global__ __launch_bounds__(256) void k_out(const float* __restrict__ bias,
                                             const float* __restrict__ gamma,
                                             const float* __restrict__ beta,
                                             float* __restrict__ out) {
    int i = blockIdx.x * 256 + threadIdx.x;
    if (i >= N_NODES * CO) return;
    int c = i & 63;
    int r = i >> 6;
    float inv_n = 1.f / (float)N_NODES;
    float mu  = g_bnsum[c] * inv_n;
    float var = g_bnsum[64 + c] * inv_n - mu * mu;
    float v = g_agg[i] * __frcp_rn(g_denom[r]) + __ldg(&bias[c]);
    float o = __ldg(&gamma[c]) * (v - mu) * rsqrtf(var + 1e-5f) + __ldg(&beta[c]);
    out[i] = o > 0.f ? o : 0.01f * o;
}

// ---------------- launch ----------------
extern "C" void kernel_launch(void* const* d_in, const int* in_sizes, int n_in,
                              void* d_out, int out_size) {
    const float* x     = (const float*)d_in[0];
    const int*   ei    = (const int*)  d_in[1];   // [2][E]
    const float* emb   = (const float*)d_in[2];
    const float* lw    = (const float*)d_in[3];
    const float* lb    = (const float*)d_in[4];
    const float* ai    = (const float*)d_in[5];
    const float* aj    = (const float*)d_in[6];
    const float* aei   = (const float*)d_in[7];
    const float* aej   = (const float*)d_in[8];
    const float* bias  = (const float*)d_in[9];
    const float* gamma = (const float*)d_in[10];
    const float* beta  = (const float*)d_in[11];

    float* out = (float*)d_out;                       // [N, 64]
    float* att = out + (size_t)N_NODES * CO;          // [ET, 1, 1]

    k_init     <<<(N_NODES * CO + 255) / 256, 256>>>();
    k_gemm     <<<(N_NODES + 127) / 128, 256>>>(x, lw, lb, emb, ai, aj, aei, aej);
    k_score_agg<<<(int)(((long long)ET * 8 + 255) / 256), 256>>>(ei);
    k_att      <<<(ET + 255) / 256, 256>>>(ei, att);
    k_stats    <<<(N_NODES + 255) / 256, 256>>>(bias);
    k_out      <<<(N_NODES * CO + 255) / 256, 256>>>(bias, gamma, beta, out);
}

// round 3
// speedup vs baseline: 1.3275x; 1.2537x over previous
#include <cuda_runtime.h>
#include <cuda_fp16.h>
#include <cstdint>

#define N_NODES 100000
#define N_EDGES 3200000
#define ET      (N_EDGES + N_NODES)   // 3,300,000 (edges + self loops)
#define CI      128
#define CO      64
#define NB_SCAN ((N_NODES + 1023) / 1024)   // 98

// ---------------- device scratch (static, no allocation) ----------------
__device__ __align__(16) __half g_xlh[(size_t)N_NODES * CO];  // 12.8 MB fp16 xl
__device__ float g_si[N_NODES];
__device__ float g_sj[N_NODES];
__device__ float g_agg[(size_t)N_NODES * CO];  // normalized aggregate
__device__ float g_bnsum[2 * CO];
__device__ int   g_deg[N_NODES];
__device__ int   g_off[N_NODES];               // exclusive prefix (CSR row ptr)
__device__ int   g_cursor[N_NODES];
__device__ int   g_bsum[NB_SCAN];
__device__ int   g_bpre[NB_SCAN];
__device__ int2  g_epack[ET];                  // (src, orig edge id) sorted by dst

// ---------------- K0: init ----------------
__global__ __launch_bounds__(256) void k_init() {
    int i = blockIdx.x * 256 + threadIdx.x;
    if (i < N_NODES) g_deg[i] = 0;
    if (i < 2 * CO) g_bnsum[i] = 0.f;
}

// ---------------- K1: GEMM xl = x @ W^T + b, fused s_i/s_j scores ------
__global__ __launch_bounds__(256) void k_gemm(
    const float* __restrict__ x,  const float* __restrict__ w,
    const float* __restrict__ lb, const float* __restrict__ emb,
    const float* __restrict__ ai, const float* __restrict__ aj,
    const float* __restrict__ aei, const float* __restrict__ aej)
{
    __shared__ float wsT[128 * 68];
    int tid = threadIdx.x;
    for (int i = tid; i < CO * CI; i += 256) {
        int c = i >> 7, k = i & 127;
        wsT[k * 68 + c] = w[i];
    }
    __syncthreads();

    int m = blockIdx.x * 128 + (tid >> 1);
    bool valid = (m < N_NODES);
    int mc = valid ? m : (N_NODES - 1);
    int g = (tid & 1) * 32;

    const float* xrow = x + (size_t)mc * CI;
    float acc[32];
#pragma unroll
    for (int c = 0; c < 32; c++) acc[c] = 0.f;

#pragma unroll 8
    for (int k0 = 0; k0 < 128; k0 += 4) {
        float4 xv = *(const float4*)(xrow + k0);
#pragma unroll
        for (int q = 0; q < 4; q++) {
            float xs = (&xv.x)[q];
            const float4* wp = (const float4*)&wsT[(k0 + q) * 68 + g];
#pragma unroll
            for (int j = 0; j < 8; j++) {
                float4 wv = wp[j];
                acc[4 * j + 0] = fmaf(xs, wv.x, acc[4 * j + 0]);
                acc[4 * j + 1] = fmaf(xs, wv.y, acc[4 * j + 1]);
                acc[4 * j + 2] = fmaf(xs, wv.z, acc[4 * j + 2]);
                acc[4 * j + 3] = fmaf(xs, wv.w, acc[4 * j + 3]);
            }
        }
    }

    float pi = 0.f, pj = 0.f;
#pragma unroll
    for (int c = 0; c < 32; c++) {
        float o = acc[c] + __ldg(&lb[g + c]);
        acc[c] = o;
        pi = fmaf(o, __ldg(&ai[g + c]), pi);
        pj = fmaf(o, __ldg(&aj[g + c]), pj);
    }
    if (valid) {
        __half2 hbuf[16];
#pragma unroll
        for (int j = 0; j < 16; j++)
            hbuf[j] = __floats2half2_rn(acc[2 * j], acc[2 * j + 1]);
        uint4* dst = (uint4*)&g_xlh[(size_t)m * CO + g];
        const uint4* src = (const uint4*)hbuf;
#pragma unroll
        for (int j = 0; j < 4; j++) dst[j] = src[j];
    }
    const float* erow = emb + (size_t)mc * CO + g;
#pragma unroll
    for (int c = 0; c < 32; c += 4) {
        float4 ev = *(const float4*)(erow + c);
        pi = fmaf(ev.x, __ldg(&aei[g + c + 0]), pi);
        pi = fmaf(ev.y, __ldg(&aei[g + c + 1]), pi);
        pi = fmaf(ev.z, __ldg(&aei[g + c + 2]), pi);
        pi = fmaf(ev.w, __ldg(&aei[g + c + 3]), pi);
        pj = fmaf(ev.x, __ldg(&aej[g + c + 0]), pj);
        pj = fmaf(ev.y, __ldg(&aej[g + c + 1]), pj);
        pj = fmaf(ev.z, __ldg(&aej[g + c + 2]), pj);
        pj = fmaf(ev.w, __ldg(&aej[g + c + 3]), pj);
    }
    pi += __shfl_xor_sync(0xffffffffu, pi, 1);
    pj += __shfl_xor_sync(0xffffffffu, pj, 1);
    if (valid && (tid & 1) == 0) { g_si[m] = pi; g_sj[m] = pj; }
}

// ---------------- CSR build: histogram, scan, scatter -------------------
__global__ __launch_bounds__(256) void k_hist(const int* __restrict__ ei) {
    int e = blockIdx.x * 256 + threadIdx.x;
    if (e >= ET) return;
    int d = (e < N_EDGES) ? __ldg(&ei[N_EDGES + e]) : (e - N_EDGES);
    atomicAdd(&g_deg[d], 1);
}

__global__ __launch_bounds__(1024) void k_blocksum() {
    __shared__ int sh[1024];
    int i = blockIdx.x * 1024 + threadIdx.x;
    sh[threadIdx.x] = (i < N_NODES) ? g_deg[i] : 0;
    __syncthreads();
    for (int s = 512; s > 0; s >>= 1) {
        if (threadIdx.x < s) sh[threadIdx.x] += sh[threadIdx.x + s];
        __syncthreads();
    }
    if (threadIdx.x == 0) g_bsum[blockIdx.x] = sh[0];
}

__global__ void k_scanbsum() {
    if (threadIdx.x == 0) {
        int acc = 0;
        for (int b = 0; b < NB_SCAN; b++) { g_bpre[b] = acc; acc += g_bsum[b]; }
    }
}

__global__ __launch_bounds__(1024) void k_scanfinal() {
    __shared__ int sh[2][1024];
    int i = blockIdx.x * 1024 + threadIdx.x;
    int t = threadIdx.x;
    int v = (i < N_NODES) ? g_deg[i] : 0;
    sh[0][t] = v;
    __syncthreads();
    int cur = 0;
#pragma unroll
    for (int ofs = 1; ofs < 1024; ofs <<= 1) {
        int nxt = cur ^ 1;
        int val = sh[cur][t];
        if (t >= ofs) val += sh[cur][t - ofs];
        sh[nxt][t] = val;
        __syncthreads();
        cur = nxt;
    }
    if (i < N_NODES) {
        int excl = sh[cur][t] - v + g_bpre[blockIdx.x];
        g_off[i] = excl;
        g_cursor[i] = excl;
    }
}

__global__ __launch_bounds__(256) void k_scatter(const int* __restrict__ ei) {
    int e = blockIdx.x * 256 + threadIdx.x;
    if (e >= ET) return;
    int s, d;
    if (e < N_EDGES) { s = __ldg(&ei[e]); d = __ldg(&ei[N_EDGES + e]); }
    else             { s = e - N_EDGES; d = s; }
    int pos = atomicAdd(&g_cursor[d], 1);
    g_epack[pos] = make_int2(s, e);
}

// ---------------- K7: CSR aggregate (one warp per dst node) ------------
// No atomics on features. Per edge: broadcast int2, broadcast s_j gather,
// coalesced 128B fp16 xl row gather. Register accumulators, in-register
// denom, normalized row write, then att[e] scatter (recompute ex, no fence).
__global__ __launch_bounds__(256) void k_agg_csr(float* __restrict__ att) {
    int warp = (blockIdx.x * 256 + threadIdx.x) >> 5;
    int lane = threadIdx.x & 31;
    if (warp >= N_NODES) return;
    int d = warp;
    int start = __ldg(&g_off[d]);
    int end = (d == N_NODES - 1) ? ET : __ldg(&g_off[d + 1]);
    float si_d = __ldg(&g_si[d]);

    float acc0 = 0.f, acc1 = 0.f, den = 0.f;
    int2 se = (start < end) ? g_epack[start] : make_int2(0, 0);
    for (int p = start; p < end; p++) {
        int2 nxt = (p + 1 < end) ? g_epack[p + 1] : make_int2(0, 0);  // prefetch
        float sj = g_sj[se.x];
        float a = si_d + sj;
        a = a > 0.f ? a : 0.2f * a;
        float ex = __expf(a);
        den += ex;
        __half2 h = *(const __half2*)&g_xlh[(size_t)se.x * CO + lane * 2];
        float2 f = __half22float2(h);
        acc0 = fmaf(ex, f.x, acc0);
        acc1 = fmaf(ex, f.y, acc1);
        se = nxt;
    }
    float rden = __frcp_rn(den);
    *(float2*)&g_agg[(size_t)d * CO + lane * 2] = make_float2(acc0 * rden, acc1 * rden);

    // attention weights in original edge order (recompute ex; deterministic)
    for (int p = start + lane; p < end; p += 32) {
        int2 pe = g_epack[p];
        float a = si_d + g_sj[pe.x];
        a = a > 0.f ? a : 0.2f * a;
        att[pe.y] = __expf(a) * rden;
    }
}

// ---------------- K8: BN statistics -------------------------------------
__global__ __launch_bounds__(256) void k_stats(const float* __restrict__ bias) {
    __shared__ float sh[512];
    int tid = threadIdx.x;
    int c = tid & 63;
    int rg = tid >> 6;
    float b = __ldg(&bias[c]);
    float s1 = 0.f, s2 = 0.f;
#pragma unroll 4
    for (int i = 0; i < 64; i++) {
        int r = blockIdx.x * 256 + rg + i * 4;
        if (r < N_NODES) {
            float v = g_agg[(size_t)r * CO + c] + b;
            s1 += v;
            s2 += v * v;
        }
    }
    sh[tid] = s1;
    sh[256 + tid] = s2;
    __syncthreads();
    if (tid < 64) {
        float t1 = sh[tid] + sh[64 + tid] + sh[128 + tid] + sh[192 + tid];
        float t2 = sh[256 + tid] + sh[320 + tid] + sh[384 + tid] + sh[448 + tid];
        atomicAdd(&g_bnsum[tid], t1);
        atomicAdd(&g_bnsum[64 + tid], t2);
    }
}

// ---------------- K9: BN apply + leaky-relu -> out ----------------------
__global__ __launch_bounds__(256) void k_out(const float* __restrict__ bias,
                                             const float* __restrict__ gamma,
                                             const float* __restrict__ beta,
                                             float* __restrict__ out) {
    int i = blockIdx.x * 256 + threadIdx.x;
    if (i >= N_NODES * CO) return;
    int c = i & 63;
    float inv_n = 1.f / (float)N_NODES;
    float mu  = g_bnsum[c] * inv_n;
    float var = g_bnsum[64 + c] * inv_n - mu * mu;
    float v = g_agg[i] + __ldg(&bias[c]);
    float o = __ldg(&gamma[c]) * (v - mu) * rsqrtf(var + 1e-5f) + __ldg(&beta[c]);
    out[i] = o > 0.f ? o : 0.01f * o;
}

// ---------------- launch ----------------
extern "C" void kernel_launch(void* const* d_in, const int* in_sizes, int n_in,
                              void* d_out, int out_size) {
    const float* x     = (const float*)d_in[0];
    const int*   ei    = (const int*)  d_in[1];
    const float* emb   = (const float*)d_in[2];
    const float* lw    = (const float*)d_in[3];
    const float* lb    = (const float*)d_in[4];
    const float* ai    = (const float*)d_in[5];
    const float* aj    = (const float*)d_in[6];
    const float* aei   = (const float*)d_in[7];
    const float* aej   = (const float*)d_in[8];
    const float* bias  = (const float*)d_in[9];
    const float* gamma = (const float*)d_in[10];
    const float* beta  = (const float*)d_in[11];

    float* out = (float*)d_out;                  // [N, 64]
    float* att = out + (size_t)N_NODES * CO;     // [ET, 1, 1]

    k_init     <<<(N_NODES + 255) / 256, 256>>>();
    k_gemm     <<<(N_NODES + 127) / 128, 256>>>(x, lw, lb, emb, ai, aj, aei, aej);
    k_hist     <<<(ET + 255) / 256, 256>>>(ei);
    k_blocksum <<<NB_SCAN, 1024>>>();
    k_scanbsum <<<1, 32>>>();
    k_scanfinal<<<NB_SCAN, 1024>>>();
    k_scatter  <<<(ET + 255) / 256, 256>>>(ei);
    k_agg_csr  <<<(N_NODES * 32 + 255) / 256, 256>>>(att);
    k_stats    <<<(N_NODES + 255) / 256, 256>>>(bias);
    k_out      <<<(N_NODES * CO + 255) / 256, 256>>>(bias, gamma, beta, out);
}

// round 4
// speedup vs baseline: 1.5062x; 1.1346x over previous
#include <cuda_runtime.h>
#include <cuda_fp16.h>
#include <cstdint>

#define N_NODES 100000
#define N_EDGES 3200000
#define ET      (N_EDGES + N_NODES)   // 3,300,000 (edges + self loops)
#define CI      128
#define CO      64
#define NB_SCAN ((N_NODES + 1023) / 1024)   // 98

// ---------------- device scratch (static, no allocation) ----------------
__device__ __align__(16) __half g_xlh[(size_t)N_NODES * CO];  // 12.8 MB fp16 xl
__device__ float g_si[N_NODES];
__device__ float g_sj[N_NODES];
__device__ float g_agg[(size_t)N_NODES * CO];
__device__ float g_bnsum[2 * CO];
__device__ int   g_deg[N_NODES];
__device__ int   g_off[N_NODES];
__device__ int   g_cursor[N_NODES];
__device__ int   g_bsum[NB_SCAN];
__device__ int   g_bpre[NB_SCAN];
__device__ int2  g_epack[ET];   // (src, float_bits(ex)) grouped by dst
__device__ int   g_eid[ET];     // original edge id, grouped by dst

// ---------------- K0: init ----------------
__global__ __launch_bounds__(256) void k_init() {
    int i = blockIdx.x * 256 + threadIdx.x;
    if (i < N_NODES) g_deg[i] = 0;
    if (i < 2 * CO) g_bnsum[i] = 0.f;
}

// ---------------- K1: GEMM xl = x @ W^T + b, fused scores --------------
// 256 threads, 256 rows/block, 2 rows per thread (wsT fragment reuse)
__global__ __launch_bounds__(256) void k_gemm(
    const float* __restrict__ x,  const float* __restrict__ w,
    const float* __restrict__ lb, const float* __restrict__ emb,
    const float* __restrict__ ai, const float* __restrict__ aj,
    const float* __restrict__ aei, const float* __restrict__ aej)
{
    __shared__ float wsT[128 * 68];   // [k][c], padded
    int tid = threadIdx.x;
    for (int i = tid; i < CO * CI; i += 256) {
        int c = i >> 7, k = i & 127;
        wsT[k * 68 + c] = w[i];
    }
    __syncthreads();

    int rbase = blockIdx.x * 256;
    int m0 = rbase + (tid >> 1);
    int m1 = m0 + 128;
    bool v0 = (m0 < N_NODES), v1 = (m1 < N_NODES);
    int mc0 = v0 ? m0 : (N_NODES - 1);
    int mc1 = v1 ? m1 : (N_NODES - 1);
    int g = (tid & 1) * 32;

    const float* xr0 = x + (size_t)mc0 * CI;
    const float* xr1 = x + (size_t)mc1 * CI;
    float acc0[32], acc1[32];
#pragma unroll
    for (int c = 0; c < 32; c++) { acc0[c] = 0.f; acc1[c] = 0.f; }

#pragma unroll 4
    for (int k0 = 0; k0 < 128; k0 += 4) {
        float4 xv0 = *(const float4*)(xr0 + k0);
        float4 xv1 = *(const float4*)(xr1 + k0);
#pragma unroll
        for (int q = 0; q < 4; q++) {
            float xs0 = (&xv0.x)[q];
            float xs1 = (&xv1.x)[q];
            const float4* wp = (const float4*)&wsT[(k0 + q) * 68 + g];
#pragma unroll
            for (int j = 0; j < 8; j++) {
                float4 wv = wp[j];
                acc0[4*j+0] = fmaf(xs0, wv.x, acc0[4*j+0]);
                acc0[4*j+1] = fmaf(xs0, wv.y, acc0[4*j+1]);
                acc0[4*j+2] = fmaf(xs0, wv.z, acc0[4*j+2]);
                acc0[4*j+3] = fmaf(xs0, wv.w, acc0[4*j+3]);
                acc1[4*j+0] = fmaf(xs1, wv.x, acc1[4*j+0]);
                acc1[4*j+1] = fmaf(xs1, wv.y, acc1[4*j+1]);
                acc1[4*j+2] = fmaf(xs1, wv.z, acc1[4*j+2]);
                acc1[4*j+3] = fmaf(xs1, wv.w, acc1[4*j+3]);
            }
        }
    }

    float pi0 = 0.f, pj0 = 0.f, pi1 = 0.f, pj1 = 0.f;
#pragma unroll
    for (int c = 0; c < 32; c++) {
        float bb = __ldg(&lb[g + c]);
        float av = __ldg(&ai[g + c]);
        float jv = __ldg(&aj[g + c]);
        float o0 = acc0[c] + bb;
        float o1 = acc1[c] + bb;
        acc0[c] = o0; acc1[c] = o1;
        pi0 = fmaf(o0, av, pi0); pj0 = fmaf(o0, jv, pj0);
        pi1 = fmaf(o1, av, pi1); pj1 = fmaf(o1, jv, pj1);
    }
    if (v0) {
        __half2 hb[16];
#pragma unroll
        for (int j = 0; j < 16; j++) hb[j] = __floats2half2_rn(acc0[2*j], acc0[2*j+1]);
        uint4* dst = (uint4*)&g_xlh[(size_t)m0 * CO + g];
#pragma unroll
        for (int j = 0; j < 4; j++) dst[j] = ((const uint4*)hb)[j];
    }
    if (v1) {
        __half2 hb[16];
#pragma unroll
        for (int j = 0; j < 16; j++) hb[j] = __floats2half2_rn(acc1[2*j], acc1[2*j+1]);
        uint4* dst = (uint4*)&g_xlh[(size_t)m1 * CO + g];
#pragma unroll
        for (int j = 0; j < 4; j++) dst[j] = ((const uint4*)hb)[j];
    }
    const float* er0 = emb + (size_t)mc0 * CO + g;
    const float* er1 = emb + (size_t)mc1 * CO + g;
#pragma unroll
    for (int c = 0; c < 32; c += 4) {
        float4 e0 = *(const float4*)(er0 + c);
        float4 e1 = *(const float4*)(er1 + c);
#pragma unroll
        for (int q = 0; q < 4; q++) {
            float aeiv = __ldg(&aei[g + c + q]);
            float aejv = __ldg(&aej[g + c + q]);
            pi0 = fmaf((&e0.x)[q], aeiv, pi0);
            pj0 = fmaf((&e0.x)[q], aejv, pj0);
            pi1 = fmaf((&e1.x)[q], aeiv, pi1);
            pj1 = fmaf((&e1.x)[q], aejv, pj1);
        }
    }
    pi0 += __shfl_xor_sync(0xffffffffu, pi0, 1);
    pj0 += __shfl_xor_sync(0xffffffffu, pj0, 1);
    pi1 += __shfl_xor_sync(0xffffffffu, pi1, 1);
    pj1 += __shfl_xor_sync(0xffffffffu, pj1, 1);
    if ((tid & 1) == 0) {
        if (v0) { g_si[m0] = pi0; g_sj[m0] = pj0; }
        if (v1) { g_si[m1] = pi1; g_sj[m1] = pj1; }
    }
}

// ---------------- CSR build: histogram, scan, scatter -------------------
__global__ __launch_bounds__(256) void k_hist(const int* __restrict__ ei) {
    int e = blockIdx.x * 256 + threadIdx.x;
    if (e >= ET) return;
    int d = (e < N_EDGES) ? __ldg(&ei[N_EDGES + e]) : (e - N_EDGES);
    atomicAdd(&g_deg[d], 1);
}

__global__ __launch_bounds__(1024) void k_blocksum() {
    __shared__ int sh[1024];
    int i = blockIdx.x * 1024 + threadIdx.x;
    sh[threadIdx.x] = (i < N_NODES) ? g_deg[i] : 0;
    __syncthreads();
    for (int s = 512; s > 0; s >>= 1) {
        if (threadIdx.x < s) sh[threadIdx.x] += sh[threadIdx.x + s];
        __syncthreads();
    }
    if (threadIdx.x == 0) g_bsum[blockIdx.x] = sh[0];
}

__global__ void k_scanbsum() {
    if (threadIdx.x == 0) {
        int acc = 0;
        for (int b = 0; b < NB_SCAN; b++) { g_bpre[b] = acc; acc += g_bsum[b]; }
    }
}

__global__ __launch_bounds__(1024) void k_scanfinal() {
    __shared__ int sh[2][1024];
    int i = blockIdx.x * 1024 + threadIdx.x;
    int t = threadIdx.x;
    int v = (i < N_NODES) ? g_deg[i] : 0;
    sh[0][t] = v;
    __syncthreads();
    int cur = 0;
#pragma unroll
    for (int ofs = 1; ofs < 1024; ofs <<= 1) {
        int nxt = cur ^ 1;
        int val = sh[cur][t];
        if (t >= ofs) val += sh[cur][t - ofs];
        sh[nxt][t] = val;
        __syncthreads();
        cur = nxt;
    }
    if (i < N_NODES) {
        int excl = sh[cur][t] - v + g_bpre[blockIdx.x];
        g_off[i] = excl;
        g_cursor[i] = excl;
    }
}

// scatter with fused score: ex precomputed so agg loop is pure gather+fma
__global__ __launch_bounds__(256) void k_scatter(const int* __restrict__ ei) {
    int e = blockIdx.x * 256 + threadIdx.x;
    if (e >= ET) return;
    int s, d;
    if (e < N_EDGES) { s = __ldg(&ei[e]); d = __ldg(&ei[N_EDGES + e]); }
    else             { s = e - N_EDGES; d = s; }
    float a = g_si[d] + g_sj[s];
    a = a > 0.f ? a : 0.2f * a;
    float ex = __expf(a);
    int pos = atomicAdd(&g_cursor[d], 1);
    g_epack[pos] = make_int2(s, __float_as_int(ex));
    g_eid[pos] = e;
}

// ---------------- K7: CSR aggregate (one warp per dst) ------------------
// 32 edges loaded coalesced per outer iter; shfl-broadcast inner loop.
__global__ __launch_bounds__(256) void k_agg_csr(float* __restrict__ att) {
    int d = (blockIdx.x * 256 + threadIdx.x) >> 5;
    int lane = threadIdx.x & 31;
    if (d >= N_NODES) return;
    int start = __ldg(&g_off[d]);
    int end = (d == N_NODES - 1) ? ET : __ldg(&g_off[d + 1]);

    float acc0 = 0.f, acc1 = 0.f, denl = 0.f;
    for (int base = start; base < end; base += 32) {
        int p = base + lane;
        int2 se = make_int2(0, 0);
        if (p < end) se = g_epack[p];
        float ex = __int_as_float(se.y);
        denl += ex;
        int cnt = min(32, end - base);
        for (int j = 0; j < cnt; j++) {
            int sj   = __shfl_sync(0xffffffffu, se.x, j);
            float xj = __shfl_sync(0xffffffffu, ex, j);
            __half2 h = *(const __half2*)&g_xlh[(size_t)sj * CO + lane * 2];
            float2 f = __half22float2(h);
            acc0 = fmaf(xj, f.x, acc0);
            acc1 = fmaf(xj, f.y, acc1);
        }
    }
#pragma unroll
    for (int o = 16; o; o >>= 1) denl += __shfl_xor_sync(0xffffffffu, denl, o);
    float rden = __frcp_rn(denl);
    *(float2*)&g_agg[(size_t)d * CO + lane * 2] = make_float2(acc0 * rden, acc1 * rden);

    for (int p = start + lane; p < end; p += 32) {
        float ex = __int_as_float(g_epack[p].y);
        att[g_eid[p]] = ex * rden;
    }
}

// ---------------- K8: BN statistics -------------------------------------
__global__ __launch_bounds__(256) void k_stats(const float* __restrict__ bias) {
    __shared__ float sh[512];
    int tid = threadIdx.x;
    int c = tid & 63;
    int rg = tid >> 6;
    float b = __ldg(&bias[c]);
    float s1 = 0.f, s2 = 0.f;
#pragma unroll 4
    for (int i = 0; i < 64; i++) {
        int r = blockIdx.x * 256 + rg + i * 4;
        if (r < N_NODES) {
            float v = g_agg[(size_t)r * CO + c] + b;
            s1 += v;
            s2 += v * v;
        }
    }
    sh[tid] = s1;
    sh[256 + tid] = s2;
    __syncthreads();
    if (tid < 64) {
        float t1 = sh[tid] + sh[64 + tid] + sh[128 + tid] + sh[192 + tid];
        float t2 = sh[256 + tid] + sh[320 + tid] + sh[384 + tid] + sh[448 + tid];
        atomicAdd(&g_bnsum[tid], t1);
        atomicAdd(&g_bnsum[64 + tid], t2);
    }
}

// ---------------- K9: BN apply + leaky-relu -> out ----------------------
__global__ __launch_bounds__(256) void k_out(const float* __restrict__ bias,
                                             const float* __restrict__ gamma,
                                             const float* __restrict__ beta,
                                             float* __restrict__ out) {
    int i = blockIdx.x * 256 + threadIdx.x;
    if (i >= N_NODES * CO) return;
    int c = i & 63;
    float inv_n = 1.f / (float)N_NODES;
    float mu  = g_bnsum[c] * inv_n;
    float var = g_bnsum[64 + c] * inv_n - mu * mu;
    float v = g_agg[i] + __ldg(&bias[c]);
    float o = __ldg(&gamma[c]) * (v - mu) * rsqrtf(var + 1e-5f) + __ldg(&beta[c]);
    out[i] = o > 0.f ? o : 0.01f * o;
}

// ---------------- launch ----------------
extern "C" void kernel_launch(void* const* d_in, const int* in_sizes, int n_in,
                              void* d_out, int out_size) {
    const float* x     = (const float*)d_in[0];
    const int*   ei    = (const int*)  d_in[1];
    const float* emb   = (const float*)d_in[2];
    const float* lw    = (const float*)d_in[3];
    const float* lb    = (const float*)d_in[4];
    const float* ai    = (const float*)d_in[5];
    const float* aj    = (const float*)d_in[6];
    const float* aei   = (const float*)d_in[7];
    const float* aej   = (const float*)d_in[8];
    const float* bias  = (const float*)d_in[9];
    const float* gamma = (const float*)d_in[10];
    const float* beta  = (const float*)d_in[11];

    float* out = (float*)d_out;                  // [N, 64]
    float* att = out + (size_t)N_NODES * CO;     // [ET, 1, 1]

    k_init     <<<(N_NODES + 255) / 256, 256>>>();
    k_gemm     <<<(N_NODES + 255) / 256, 256>>>(x, lw, lb, emb, ai, aj, aei, aej);
    k_hist     <<<(ET + 255) / 256, 256>>>(ei);
    k_blocksum <<<NB_SCAN, 1024>>>();
    k_scanbsum <<<1, 32>>>();
    k_scanfinal<<<NB_SCAN, 1024>>>();
    k_scatter  <<<(ET + 255) / 256, 256>>>(ei);
    k_agg_csr  <<<(N_NODES * 32 + 255) / 256, 256>>>(att);
    k_stats    <<<(N_NODES + 255) / 256, 256>>>(bias);
    k_out      <<<(N_NODES * CO + 255) / 256, 256>>>(bias, gamma, beta, out);
}

// round 5
// speedup vs baseline: 1.5394x; 1.0221x over previous
#include <cuda_runtime.h>
#include <cuda_fp16.h>
#include <cstdint>

#define N_NODES 100000
#define N_EDGES 3200000
#define ET      (N_EDGES + N_NODES)   // 3,300,000 (edges + self loops)
#define CI      128
#define CO      64
#define NB_SCAN ((N_NODES + 1023) / 1024)   // 98

// ---------------- device scratch (static, no allocation) ----------------
__device__ __align__(16) __half g_xlh[(size_t)N_NODES * CO];  // 12.8 MB fp16 xl
__device__ float g_si[N_NODES];
__device__ float g_sj[N_NODES];
__device__ float g_agg[(size_t)N_NODES * CO];   // normalized + bias
__device__ float g_bnsum[2 * CO];
__device__ int   g_deg[N_NODES];
__device__ int   g_off[N_NODES];
__device__ int   g_cursor[N_NODES];
__device__ int   g_bsum[NB_SCAN];
__device__ int   g_bpre[NB_SCAN];
__device__ int2  g_epack[ET];   // (src, float_bits(ex)) grouped by dst
__device__ int   g_eid[ET];     // original edge id, grouped by dst

// ---------------- packed f32x2 helpers ----------------
__device__ __forceinline__ unsigned long long pk2(float lo, float hi) {
    unsigned long long r;
    asm("mov.b64 %0, {%1, %2};" : "=l"(r) : "f"(lo), "f"(hi));
    return r;
}
__device__ __forceinline__ float2 upk2(unsigned long long v) {
    float2 f;
    asm("mov.b64 {%0, %1}, %2;" : "=f"(f.x), "=f"(f.y) : "l"(v));
    return f;
}
#define FMA2(d, a, b) asm("fma.rn.f32x2 %0, %1, %2, %0;" : "+l"(d) : "l"(a), "l"(b))

// ---------------- K0: init ----------------
__global__ __launch_bounds__(256) void k_init() {
    int i = blockIdx.x * 256 + threadIdx.x;
    if (i < N_NODES) g_deg[i] = 0;
    if (i < 2 * CO) g_bnsum[i] = 0.f;
}

// ---------------- K1: GEMM xl = x @ W^T + b, fused scores --------------
// 128 threads/block, 256 rows/block, 4 rows/thread, f32x2 packed FMA.
__global__ __launch_bounds__(128) void k_gemm(
    const float* __restrict__ x,  const float* __restrict__ w,
    const float* __restrict__ lb, const float* __restrict__ emb,
    const float* __restrict__ ai, const float* __restrict__ aj,
    const float* __restrict__ aei, const float* __restrict__ aej)
{
    __shared__ float wsT[128 * 68];   // [k][c], padded row = 68 floats
    int tid = threadIdx.x;
    for (int i = tid; i < CO * CI; i += 128) {
        int c = i >> 7, k = i & 127;  // w is [CO][CI] row-major
        wsT[k * 68 + c] = w[i];
    }
    __syncthreads();

    int rbase = blockIdx.x * 256;
    int t2 = tid >> 1;                 // 0..63
    int g = (tid & 1) * 32;            // column half
    int m[4]; bool v[4]; int mc[4];
#pragma unroll
    for (int r = 0; r < 4; r++) {
        m[r] = rbase + t2 + r * 64;
        v[r] = (m[r] < N_NODES);
        mc[r] = v[r] ? m[r] : (N_NODES - 1);
    }

    const float* xr0 = x + (size_t)mc[0] * CI;
    const float* xr1 = x + (size_t)mc[1] * CI;
    const float* xr2 = x + (size_t)mc[2] * CI;
    const float* xr3 = x + (size_t)mc[3] * CI;

    unsigned long long acc[4][16];
#pragma unroll
    for (int r = 0; r < 4; r++)
#pragma unroll
        for (int t = 0; t < 16; t++) acc[r][t] = 0ull;

    for (int k0 = 0; k0 < 128; k0 += 4) {
        float4 xv0 = *(const float4*)(xr0 + k0);
        float4 xv1 = *(const float4*)(xr1 + k0);
        float4 xv2 = *(const float4*)(xr2 + k0);
        float4 xv3 = *(const float4*)(xr3 + k0);
#pragma unroll
        for (int q = 0; q < 4; q++) {
            unsigned long long xs0 = pk2((&xv0.x)[q], (&xv0.x)[q]);
            unsigned long long xs1 = pk2((&xv1.x)[q], (&xv1.x)[q]);
            unsigned long long xs2 = pk2((&xv2.x)[q], (&xv2.x)[q]);
            unsigned long long xs3 = pk2((&xv3.x)[q], (&xv3.x)[q]);
            const float4* wp = (const float4*)&wsT[(k0 + q) * 68 + g];
#pragma unroll
            for (int j = 0; j < 8; j++) {
                float4 wv = wp[j];
                unsigned long long w01 = pk2(wv.x, wv.y);
                unsigned long long w23 = pk2(wv.z, wv.w);
                FMA2(acc[0][2*j],   xs0, w01); FMA2(acc[0][2*j+1], xs0, w23);
                FMA2(acc[1][2*j],   xs1, w01); FMA2(acc[1][2*j+1], xs1, w23);
                FMA2(acc[2][2*j],   xs2, w01); FMA2(acc[2][2*j+1], xs2, w23);
                FMA2(acc[3][2*j],   xs3, w01); FMA2(acc[3][2*j+1], xs3, w23);
            }
        }
    }

    // epilogue per row: bias, scores, fp16 xl store
#pragma unroll
    for (int r = 0; r < 4; r++) {
        float p_i = 0.f, p_j = 0.f;
        unsigned hu[16];
#pragma unroll
        for (int t = 0; t < 16; t++) {
            float2 f = upk2(acc[r][t]);
            float o0 = f.x + __ldg(&lb[g + 2*t]);
            float o1 = f.y + __ldg(&lb[g + 2*t + 1]);
            p_i = fmaf(o0, __ldg(&ai[g + 2*t]),     p_i);
            p_i = fmaf(o1, __ldg(&ai[g + 2*t + 1]), p_i);
            p_j = fmaf(o0, __ldg(&aj[g + 2*t]),     p_j);
            p_j = fmaf(o1, __ldg(&aj[g + 2*t + 1]), p_j);
            __half2 hh = __floats2half2_rn(o0, o1);
            hu[t] = *reinterpret_cast<unsigned*>(&hh);
        }
        if (v[r]) {
            uint4* dstp = (uint4*)&g_xlh[(size_t)m[r] * CO + g];
            dstp[0] = make_uint4(hu[0],  hu[1],  hu[2],  hu[3]);
            dstp[1] = make_uint4(hu[4],  hu[5],  hu[6],  hu[7]);
            dstp[2] = make_uint4(hu[8],  hu[9],  hu[10], hu[11]);
            dstp[3] = make_uint4(hu[12], hu[13], hu[14], hu[15]);
        }
        const float* er = emb + (size_t)mc[r] * CO + g;
#pragma unroll
        for (int c = 0; c < 32; c += 4) {
            float4 ev = *(const float4*)(er + c);
#pragma unroll
            for (int q = 0; q < 4; q++) {
                p_i = fmaf((&ev.x)[q], __ldg(&aei[g + c + q]), p_i);
                p_j = fmaf((&ev.x)[q], __ldg(&aej[g + c + q]), p_j);
            }
        }
        p_i += __shfl_xor_sync(0xffffffffu, p_i, 1);
        p_j += __shfl_xor_sync(0xffffffffu, p_j, 1);
        if (v[r] && (tid & 1) == 0) { g_si[m[r]] = p_i; g_sj[m[r]] = p_j; }
    }
}

// ---------------- CSR build: histogram, scan, scatter -------------------
__global__ __launch_bounds__(256) void k_hist(const int* __restrict__ ei) {
    int e = blockIdx.x * 256 + threadIdx.x;
    if (e >= ET) return;
    int d = (e < N_EDGES) ? __ldg(&ei[N_EDGES + e]) : (e - N_EDGES);
    atomicAdd(&g_deg[d], 1);
}

__global__ __launch_bounds__(1024) void k_blocksum() {
    __shared__ int sh[1024];
    int i = blockIdx.x * 1024 + threadIdx.x;
    sh[threadIdx.x] = (i < N_NODES) ? g_deg[i] : 0;
    __syncthreads();
    for (int s = 512; s > 0; s >>= 1) {
        if (threadIdx.x < s) sh[threadIdx.x] += sh[threadIdx.x + s];
        __syncthreads();
    }
    if (threadIdx.x == 0) g_bsum[blockIdx.x] = sh[0];
}

__global__ void k_scanbsum() {
    if (threadIdx.x == 0) {
        int acc = 0;
        for (int b = 0; b < NB_SCAN; b++) { g_bpre[b] = acc; acc += g_bsum[b]; }
    }
}

__global__ __launch_bounds__(1024) void k_scanfinal() {
    __shared__ int sh[2][1024];
    int i = blockIdx.x * 1024 + threadIdx.x;
    int t = threadIdx.x;
    int v = (i < N_NODES) ? g_deg[i] : 0;
    sh[0][t] = v;
    __syncthreads();
    int cur = 0;
#pragma unroll
    for (int ofs = 1; ofs < 1024; ofs <<= 1) {
        int nxt = cur ^ 1;
        int val = sh[cur][t];
        if (t >= ofs) val += sh[cur][t - ofs];
        sh[nxt][t] = val;
        __syncthreads();
        cur = nxt;
    }
    if (i < N_NODES) {
        int excl = sh[cur][t] - v + g_bpre[blockIdx.x];
        g_off[i] = excl;
        g_cursor[i] = excl;
    }
}

// scatter with fused score: ex precomputed so agg loop is pure gather+fma
__global__ __launch_bounds__(256) void k_scatter(const int* __restrict__ ei) {
    int e = blockIdx.x * 256 + threadIdx.x;
    if (e >= ET) return;
    int s, d;
    if (e < N_EDGES) { s = __ldg(&ei[e]); d = __ldg(&ei[N_EDGES + e]); }
    else             { s = e - N_EDGES; d = s; }
    float a = g_si[d] + g_sj[s];
    a = a > 0.f ? a : 0.2f * a;
    float ex = __expf(a);
    int pos = atomicAdd(&g_cursor[d], 1);
    g_epack[pos] = make_int2(s, __float_as_int(ex));
    g_eid[pos] = e;
}

// ---------------- K7: CSR aggregate + fused BN stats --------------------
// One warp per dst node; grid is EXACTLY 12500 blocks (100000 warps).
__global__ __launch_bounds__(256) void k_agg_csr(float* __restrict__ att,
                                                 const float* __restrict__ bias) {
    __shared__ float bs1[64], bs2[64];
    int tid = threadIdx.x;
    if (tid < 64) { bs1[tid] = 0.f; bs2[tid] = 0.f; }
    __syncthreads();

    int d = (blockIdx.x * 256 + tid) >> 5;
    int lane = tid & 31;
    int start = __ldg(&g_off[d]);
    int end = (d == N_NODES - 1) ? ET : __ldg(&g_off[d + 1]);

    float acc0 = 0.f, acc1 = 0.f, denl = 0.f;
    int base = start;
    // fast path: full 32-edge chunks, unrolled inner loop
    for (; base + 32 <= end; base += 32) {
        int2 se = g_epack[base + lane];
        float ex = __int_as_float(se.y);
        denl += ex;
#pragma unroll 8
        for (int j = 0; j < 32; j++) {
            int sj   = __shfl_sync(0xffffffffu, se.x, j);
            float xj = __shfl_sync(0xffffffffu, ex, j);
            __half2 h = *(const __half2*)&g_xlh[(size_t)sj * CO + lane * 2];
            float2 f = __half22float2(h);
            acc0 = fmaf(xj, f.x, acc0);
            acc1 = fmaf(xj, f.y, acc1);
        }
    }
    if (base < end) {
        int p = base + lane;
        int2 se = (p < end) ? g_epack[p] : make_int2(0, 0);
        float ex = __int_as_float(se.y);   // 0 bits -> 0.0f
        denl += ex;
        int cnt = end - base;
        for (int j = 0; j < cnt; j++) {
            int sj   = __shfl_sync(0xffffffffu, se.x, j);
            float xj = __shfl_sync(0xffffffffu, ex, j);
            __half2 h = *(const __half2*)&g_xlh[(size_t)sj * CO + lane * 2];
            float2 f = __half22float2(h);
            acc0 = fmaf(xj, f.x, acc0);
            acc1 = fmaf(xj, f.y, acc1);
        }
    }
#pragma unroll
    for (int o = 16; o; o >>= 1) denl += __shfl_xor_sync(0xffffffffu, denl, o);
    float rden = __frcp_rn(denl);
    float r0 = acc0 * rden + __ldg(&bias[2 * lane]);
    float r1 = acc1 * rden + __ldg(&bias[2 * lane + 1]);
    *(float2*)&g_agg[(size_t)d * CO + lane * 2] = make_float2(r0, r1);

    // BN partial sums (block-local smem, spread addresses)
    atomicAdd(&bs1[2 * lane],     r0);
    atomicAdd(&bs1[2 * lane + 1], r1);
    atomicAdd(&bs2[2 * lane],     r0 * r0);
    atomicAdd(&bs2[2 * lane + 1], r1 * r1);

    // attention weights in original edge order
    for (int p = start + lane; p < end; p += 32) {
        float exv = __int_as_float(g_epack[p].y);
        att[g_eid[p]] = exv * rden;
    }

    __syncthreads();
    if (tid < 64) {
        atomicAdd(&g_bnsum[tid],      bs1[tid]);
        atomicAdd(&g_bnsum[64 + tid], bs2[tid]);
    }
}

// ---------------- K8: BN apply + leaky-relu -> out ----------------------
__global__ __launch_bounds__(256) void k_out(const float* __restrict__ gamma,
                                             const float* __restrict__ beta,
                                             float* __restrict__ out) {
    int i = blockIdx.x * 256 + threadIdx.x;
    if (i >= N_NODES * CO) return;
    int c = i & 63;
    float inv_n = 1.f / (float)N_NODES;
    float mu  = g_bnsum[c] * inv_n;
    float var = g_bnsum[64 + c] * inv_n - mu * mu;
    float v = g_agg[i];   // already includes bias
    float o = __ldg(&gamma[c]) * (v - mu) * rsqrtf(var + 1e-5f) + __ldg(&beta[c]);
    out[i] = o > 0.f ? o : 0.01f * o;
}

// ---------------- launch ----------------
extern "C" void kernel_launch(void* const* d_in, const int* in_sizes, int n_in,
                              void* d_out, int out_size) {
    const float* x     = (const float*)d_in[0];
    const int*   ei    = (const int*)  d_in[1];
    const float* emb   = (const float*)d_in[2];
    const float* lw    = (const float*)d_in[3];
    const float* lb    = (const float*)d_in[4];
    const float* ai    = (const float*)d_in[5];
    const float* aj    = (const float*)d_in[6];
    const float* aei   = (const float*)d_in[7];
    const float* aej   = (const float*)d_in[8];
    const float* bias  = (const float*)d_in[9];
    const float* gamma = (const float*)d_in[10];
    const float* beta  = (const float*)d_in[11];

    float* out = (float*)d_out;                  // [N, 64]
    float* att = out + (size_t)N_NODES * CO;     // [ET, 1, 1]

    k_init     <<<(N_NODES + 255) / 256, 256>>>();
    k_gemm     <<<(N_NODES + 255) / 256, 128>>>(x, lw, lb, emb, ai, aj, aei, aej);
    k_hist     <<<(ET + 255) / 256, 256>>>(ei);
    k_blocksum <<<NB_SCAN, 1024>>>();
    k_scanbsum <<<1, 32>>>();
    k_scanfinal<<<NB_SCAN, 1024>>>();
    k_scatter  <<<(ET + 255) / 256, 256>>>(ei);
    k_agg_csr  <<<(N_NODES * 32) / 256, 256>>>(att, bias);
    k_out      <<<(N_NODES * CO + 255) / 256, 256>>>(gamma, beta, out);
}

// round 6
// speedup vs baseline: 1.6450x; 1.0686x over previous
#include <cuda_runtime.h>
#include <cuda_fp16.h>
#include <cstdint>

#define N_NODES 100000
#define N_EDGES 3200000
#define ET      (N_EDGES + N_NODES)   // 3,300,000 (edges + self loops)
#define CI      128
#define CO      64
#define NB_SCAN ((N_NODES + 1023) / 1024)   // 98

// ---------------- device scratch (static, no allocation) ----------------
__device__ __align__(16) __half g_xlh[(size_t)N_NODES * CO];  // 12.8 MB fp16 xl
__device__ float g_si[N_NODES];
__device__ float g_sj[N_NODES];
__device__ float g_rden[N_NODES];
__device__ float g_agg[(size_t)N_NODES * CO];   // normalized + bias
__device__ float g_bnsum[2 * CO];
__device__ int   g_deg[N_NODES];
__device__ int   g_off[N_NODES];
__device__ int   g_cursor[N_NODES];
__device__ int   g_bsum[NB_SCAN];
__device__ int   g_bpre[NB_SCAN];
__device__ int2  g_epack[ET];    // (src, float_bits(ex)) grouped by dst
__device__ float g_exorig[ET];   // ex in ORIGINAL edge order (coalesced)

// ---------------- packed f32x2 helpers ----------------
__device__ __forceinline__ unsigned long long pk2(float lo, float hi) {
    unsigned long long r;
    asm("mov.b64 %0, {%1, %2};" : "=l"(r) : "f"(lo), "f"(hi));
    return r;
}
__device__ __forceinline__ float2 upk2(unsigned long long v) {
    float2 f;
    asm("mov.b64 {%0, %1}, %2;" : "=f"(f.x), "=f"(f.y) : "l"(v));
    return f;
}
#define FMA2(d, a, b) asm("fma.rn.f32x2 %0, %1, %2, %0;" : "+l"(d) : "l"(a), "l"(b))

// ---------------- K0: init ----------------
__global__ __launch_bounds__(256) void k_init() {
    int i = blockIdx.x * 256 + threadIdx.x;
    if (i < N_NODES) g_deg[i] = 0;
    if (i < 2 * CO) g_bnsum[i] = 0.f;
}

// ---------------- K1: GEMM xl = x @ W^T + b, fused scores --------------
// 256 thr/block, 256 rows/block; thread = 4 rows x 16 cols; f32x2 FMA.
__global__ __launch_bounds__(256) void k_gemm(
    const float* __restrict__ x,  const float* __restrict__ w,
    const float* __restrict__ lb, const float* __restrict__ emb,
    const float* __restrict__ ai, const float* __restrict__ aj,
    const float* __restrict__ aei, const float* __restrict__ aej)
{
    __shared__ float wsT[128 * 68];   // [k][c], row padded to 68 floats
    int tid = threadIdx.x;
    for (int i = tid; i < CO * CI; i += 256) {
        int c = i >> 7, k = i & 127;  // w is [CO][CI] row-major
        wsT[k * 68 + c] = w[i];
    }
    __syncthreads();

    int rbase = blockIdx.x * 256;
    int rl = tid >> 2;                 // 0..63
    int g = (tid & 3) * 16;            // 16-col group
    int m[4]; bool v[4]; int mc[4];
#pragma unroll
    for (int r = 0; r < 4; r++) {
        m[r] = rbase + rl + r * 64;
        v[r] = (m[r] < N_NODES);
        mc[r] = v[r] ? m[r] : (N_NODES - 1);
    }
    const float* xr0 = x + (size_t)mc[0] * CI;
    const float* xr1 = x + (size_t)mc[1] * CI;
    const float* xr2 = x + (size_t)mc[2] * CI;
    const float* xr3 = x + (size_t)mc[3] * CI;

    unsigned long long acc[4][8];      // 4 rows x 8 f32x2 = 16 cols
#pragma unroll
    for (int r = 0; r < 4; r++)
#pragma unroll
        for (int t = 0; t < 8; t++) acc[r][t] = 0ull;

    for (int k0 = 0; k0 < 128; k0 += 4) {
        float4 xv0 = *(const float4*)(xr0 + k0);
        float4 xv1 = *(const float4*)(xr1 + k0);
        float4 xv2 = *(const float4*)(xr2 + k0);
        float4 xv3 = *(const float4*)(xr3 + k0);
#pragma unroll
        for (int q = 0; q < 4; q++) {
            unsigned long long xs0 = pk2((&xv0.x)[q], (&xv0.x)[q]);
            unsigned long long xs1 = pk2((&xv1.x)[q], (&xv1.x)[q]);
            unsigned long long xs2 = pk2((&xv2.x)[q], (&xv2.x)[q]);
            unsigned long long xs3 = pk2((&xv3.x)[q], (&xv3.x)[q]);
            const ulonglong2* wp = (const ulonglong2*)&wsT[(k0 + q) * 68 + g];
#pragma unroll
            for (int j = 0; j < 4; j++) {
                ulonglong2 wv = wp[j];               // LDS.128 = 2 packed pairs
                FMA2(acc[0][2*j],   xs0, wv.x); FMA2(acc[0][2*j+1], xs0, wv.y);
                FMA2(acc[1][2*j],   xs1, wv.x); FMA2(acc[1][2*j+1], xs1, wv.y);
                FMA2(acc[2][2*j],   xs2, wv.x); FMA2(acc[2][2*j+1], xs2, wv.y);
                FMA2(acc[3][2*j],   xs3, wv.x); FMA2(acc[3][2*j+1], xs3, wv.y);
            }
        }
    }

    // epilogue per row: bias, scores, fp16 xl store; reduce over 4 lanes
#pragma unroll
    for (int r = 0; r < 4; r++) {
        float p_i = 0.f, p_j = 0.f;
        unsigned hu[8];
#pragma unroll
        for (int t = 0; t < 8; t++) {
            float2 f = upk2(acc[r][t]);
            float o0 = f.x + __ldg(&lb[g + 2*t]);
            float o1 = f.y + __ldg(&lb[g + 2*t + 1]);
            p_i = fmaf(o0, __ldg(&ai[g + 2*t]),     p_i);
            p_i = fmaf(o1, __ldg(&ai[g + 2*t + 1]), p_i);
            p_j = fmaf(o0, __ldg(&aj[g + 2*t]),     p_j);
            p_j = fmaf(o1, __ldg(&aj[g + 2*t + 1]), p_j);
            __half2 hh = __floats2half2_rn(o0, o1);
            hu[t] = *reinterpret_cast<unsigned*>(&hh);
        }
        if (v[r]) {
            uint4* dstp = (uint4*)&g_xlh[(size_t)m[r] * CO + g];
            dstp[0] = make_uint4(hu[0], hu[1], hu[2], hu[3]);
            dstp[1] = make_uint4(hu[4], hu[5], hu[6], hu[7]);
        }
        const float* er = emb + (size_t)mc[r] * CO + g;
#pragma unroll
        for (int c = 0; c < 16; c += 4) {
            float4 ev = *(const float4*)(er + c);
#pragma unroll
            for (int q = 0; q < 4; q++) {
                p_i = fmaf((&ev.x)[q], __ldg(&aei[g + c + q]), p_i);
                p_j = fmaf((&ev.x)[q], __ldg(&aej[g + c + q]), p_j);
            }
        }
        p_i += __shfl_xor_sync(0xffffffffu, p_i, 1);
        p_j += __shfl_xor_sync(0xffffffffu, p_j, 1);
        p_i += __shfl_xor_sync(0xffffffffu, p_i, 2);
        p_j += __shfl_xor_sync(0xffffffffu, p_j, 2);
        if (v[r] && (tid & 3) == 0) { g_si[m[r]] = p_i; g_sj[m[r]] = p_j; }
    }
}

// ---------------- CSR build: histogram, scan, scatter -------------------
__global__ __launch_bounds__(256) void k_hist(const int* __restrict__ ei) {
    int e = blockIdx.x * 256 + threadIdx.x;
    if (e >= ET) return;
    int d = (e < N_EDGES) ? __ldg(&ei[N_EDGES + e]) : (e - N_EDGES);
    atomicAdd(&g_deg[d], 1);
}

__global__ __launch_bounds__(1024) void k_blocksum() {
    __shared__ int sh[1024];
    int i = blockIdx.x * 1024 + threadIdx.x;
    sh[threadIdx.x] = (i < N_NODES) ? g_deg[i] : 0;
    __syncthreads();
    for (int s = 512; s > 0; s >>= 1) {
        if (threadIdx.x < s) sh[threadIdx.x] += sh[threadIdx.x + s];
        __syncthreads();
    }
    if (threadIdx.x == 0) g_bsum[blockIdx.x] = sh[0];
}

__global__ void k_scanbsum() {
    if (threadIdx.x == 0) {
        int acc = 0;
        for (int b = 0; b < NB_SCAN; b++) { g_bpre[b] = acc; acc += g_bsum[b]; }
    }
}

__global__ __launch_bounds__(1024) void k_scanfinal() {
    __shared__ int sh[2][1024];
    int i = blockIdx.x * 1024 + threadIdx.x;
    int t = threadIdx.x;
    int v = (i < N_NODES) ? g_deg[i] : 0;
    sh[0][t] = v;
    __syncthreads();
    int cur = 0;
#pragma unroll
    for (int ofs = 1; ofs < 1024; ofs <<= 1) {
        int nxt = cur ^ 1;
        int val = sh[cur][t];
        if (t >= ofs) val += sh[cur][t - ofs];
        sh[nxt][t] = val;
        __syncthreads();
        cur = nxt;
    }
    if (i < N_NODES) {
        int excl = sh[cur][t] - v + g_bpre[blockIdx.x];
        g_off[i] = excl;
        g_cursor[i] = excl;
    }
}

// scatter: compute ex once; random epack store + coalesced exorig store
__global__ __launch_bounds__(256) void k_scatter(const int* __restrict__ ei) {
    int e = blockIdx.x * 256 + threadIdx.x;
    if (e >= ET) return;
    int s, d;
    if (e < N_EDGES) { s = __ldg(&ei[e]); d = __ldg(&ei[N_EDGES + e]); }
    else             { s = e - N_EDGES; d = s; }
    float a = g_si[d] + g_sj[s];
    a = a > 0.f ? a : 0.2f * a;
    float ex = __expf(a);
    g_exorig[e] = ex;                        // coalesced
    int pos = atomicAdd(&g_cursor[d], 1);
    g_epack[pos] = make_int2(s, __float_as_int(ex));
}

// ---------------- K7: CSR aggregate + fused BN stats --------------------
// One warp per dst node; grid is EXACTLY 12500 blocks (100000 warps).
__global__ __launch_bounds__(256) void k_agg_csr(const float* __restrict__ bias) {
    __shared__ float bs1[64], bs2[64];
    int tid = threadIdx.x;
    if (tid < 64) { bs1[tid] = 0.f; bs2[tid] = 0.f; }
    __syncthreads();

    int d = (blockIdx.x * 256 + tid) >> 5;
    int lane = tid & 31;
    int start = __ldg(&g_off[d]);
    int end = (d == N_NODES - 1) ? ET : __ldg(&g_off[d + 1]);

    float acc0 = 0.f, acc1 = 0.f, denl = 0.f;
    int base = start;
    for (; base + 32 <= end; base += 32) {          // full-chunk fast path
        int2 se = g_epack[base + lane];
        float ex = __int_as_float(se.y);
        denl += ex;
#pragma unroll 8
        for (int j = 0; j < 32; j++) {
            int sj   = __shfl_sync(0xffffffffu, se.x, j);
            float xj = __shfl_sync(0xffffffffu, ex, j);
            __half2 h = *(const __half2*)&g_xlh[(size_t)sj * CO + lane * 2];
            float2 f = __half22float2(h);
            acc0 = fmaf(xj, f.x, acc0);
            acc1 = fmaf(xj, f.y, acc1);
        }
    }
    if (base < end) {
        int p = base + lane;
        int2 se = (p < end) ? g_epack[p] : make_int2(0, 0);
        float ex = __int_as_float(se.y);
        denl += ex;
        int cnt = end - base;
        for (int j = 0; j < cnt; j++) {
            int sj   = __shfl_sync(0xffffffffu, se.x, j);
            float xj = __shfl_sync(0xffffffffu, ex, j);
            __half2 h = *(const __half2*)&g_xlh[(size_t)sj * CO + lane * 2];
            float2 f = __half22float2(h);
            acc0 = fmaf(xj, f.x, acc0);
            acc1 = fmaf(xj, f.y, acc1);
        }
    }
#pragma unroll
    for (int o = 16; o; o >>= 1) denl += __shfl_xor_sync(0xffffffffu, denl, o);
    float rden = __frcp_rn(denl);
    if (lane == 0) g_rden[d] = rden;
    float r0 = acc0 * rden + __ldg(&bias[2 * lane]);
    float r1 = acc1 * rden + __ldg(&bias[2 * lane + 1]);
    *(float2*)&g_agg[(size_t)d * CO + lane * 2] = make_float2(r0, r1);

    atomicAdd(&bs1[2 * lane],     r0);
    atomicAdd(&bs1[2 * lane + 1], r1);
    atomicAdd(&bs2[2 * lane],     r0 * r0);
    atomicAdd(&bs2[2 * lane + 1], r1 * r1);

    __syncthreads();
    if (tid < 64) {
        atomicAdd(&g_bnsum[tid],      bs1[tid]);
        atomicAdd(&g_bnsum[64 + tid], bs2[tid]);
    }
}

// ---------------- K8: attention weights (coalesced) --------------------
__global__ __launch_bounds__(256) void k_att(const int* __restrict__ ei,
                                             float* __restrict__ att) {
    int e = blockIdx.x * 256 + threadIdx.x;
    if (e >= ET) return;
    int d = (e < N_EDGES) ? __ldg(&ei[N_EDGES + e]) : (e - N_EDGES);
    att[e] = g_exorig[e] * g_rden[d];
}

// ---------------- K9: BN apply + leaky-relu -> out ----------------------
__global__ __launch_bounds__(256) void k_out(const float* __restrict__ gamma,
                                             const float* __restrict__ beta,
                                             float* __restrict__ out) {
    int i = blockIdx.x * 256 + threadIdx.x;
    if (i >= N_NODES * CO) return;
    int c = i & 63;
    float inv_n = 1.f / (float)N_NODES;
    float mu  = g_bnsum[c] * inv_n;
    float var = g_bnsum[64 + c] * inv_n - mu * mu;
    float v = g_agg[i];   // already includes bias
    float o = __ldg(&gamma[c]) * (v - mu) * rsqrtf(var + 1e-5f) + __ldg(&beta[c]);
    out[i] = o > 0.f ? o : 0.01f * o;
}

// ---------------- launch ----------------
extern "C" void kernel_launch(void* const* d_in, const int* in_sizes, int n_in,
                              void* d_out, int out_size) {
    const float* x     = (const float*)d_in[0];
    const int*   ei    = (const int*)  d_in[1];
    const float* emb   = (const float*)d_in[2];
    const float* lw    = (const float*)d_in[3];
    const float* lb    = (const float*)d_in[4];
    const float* ai    = (const float*)d_in[5];
    const float* aj    = (const float*)d_in[6];
    const float* aei   = (const float*)d_in[7];
    const float* aej   = (const float*)d_in[8];
    const float* bias  = (const float*)d_in[9];
    const float* gamma = (const float*)d_in[10];
    const float* beta  = (const float*)d_in[11];

    float* out = (float*)d_out;                  // [N, 64]
    float* att = out + (size_t)N_NODES * CO;     // [ET, 1, 1]

    k_init     <<<(N_NODES + 255) / 256, 256>>>();
    k_gemm     <<<(N_NODES + 255) / 256, 256>>>(x, lw, lb, emb, ai, aj, aei, aej);
    k_hist     <<<(ET + 255) / 256, 256>>>(ei);
    k_blocksum <<<NB_SCAN, 1024>>>();
    k_scanbsum <<<1, 32>>>();
    k_scanfinal<<<NB_SCAN, 1024>>>();
    k_scatter  <<<(ET + 255) / 256, 256>>>(ei);
    k_agg_csr  <<<(N_NODES * 32) / 256, 256>>>(bias);
    k_att      <<<(ET + 255) / 256, 256>>>(ei, att);
    k_out      <<<(N_NODES * CO + 255) / 256, 256>>>(gamma, beta, out);
}